// round 2
// baseline (speedup 1.0000x reference)
#include <cuda_runtime.h>
#include <math.h>
#include <stdint.h>

#define NN   100000
#define NE   1600000
#define HID  64
#define K1   136          // 2*HID + EDGE_IN
#define TILE_E 128
#define MLP_GRID 592

// ---------------- scratch (static device allocations, allowed) ----------------
__device__ float g_deg[NN];
__device__ float g_sum[NN * HID];
__device__ float g_hA[NN * HID];
__device__ float g_hB[NN * HID];

// ---------------- degree count ----------------
__global__ void k_deg(const int* __restrict__ dst) {
    int e = blockIdx.x * blockDim.x + threadIdx.x;
    if (e < NE) atomicAdd(&g_deg[dst[e]], 1.0f);
}

// ---------------- scatter-add of h[src] rows into g_sum[dst] ----------------
template <int F>
__global__ void k_scatter(const float* __restrict__ h,
                          const int* __restrict__ src,
                          const int* __restrict__ dst) {
    const int C = F / 4;                       // float4 chunks per row
    int idx = blockIdx.x * blockDim.x + threadIdx.x;
    if (idx >= NE * C) return;
    int e = idx / C;
    int c = idx - e * C;
    int s = __ldg(&src[e]);
    int d = __ldg(&dst[e]);
    float4 v = *reinterpret_cast<const float4*>(h + (size_t)s * F + (size_t)c * 4);
    float* p = g_sum + (size_t)d * F + (size_t)c * 4;
    // vectorized fp32 reduction (sm_90+): 4x fewer LTS atomic ops than scalar
    asm volatile("red.global.add.v4.f32 [%0], {%1,%2,%3,%4};"
                 :: "l"(p), "f"(v.x), "f"(v.y), "f"(v.z), "f"(v.w) : "memory");
}

// ---------------- node transform: out = [relu]( (sum*inv)@Wl + bl + hin@Wr ) ----------------
template <int IN, bool RELU>
__global__ __launch_bounds__(128)
void k_node(const float* __restrict__ hin,
            const float* __restrict__ Wl, const float* __restrict__ bl,
            const float* __restrict__ Wr,
            float* __restrict__ hout) {
    __shared__ float sWl[IN * HID];
    __shared__ float sWr[IN * HID];
    __shared__ float sB[HID];
    for (int i = threadIdx.x; i < IN * HID; i += blockDim.x) {
        sWl[i] = Wl[i];
        sWr[i] = Wr[i];
    }
    if (threadIdx.x < HID) sB[threadIdx.x] = bl[threadIdx.x];
    __syncthreads();

    int n = blockIdx.x * blockDim.x + threadIdx.x;
    if (n >= NN) return;

    float inv = 1.0f / fmaxf(g_deg[n], 1.0f);

    float acc[HID];
#pragma unroll
    for (int j = 0; j < HID; j++) acc[j] = sB[j];

    const float4* sumv = reinterpret_cast<const float4*>(g_sum + (size_t)n * IN);
    const float4* xv   = reinterpret_cast<const float4*>(hin   + (size_t)n * IN);

#pragma unroll 1
    for (int kc = 0; kc < IN / 4; kc++) {
        float4 mv = sumv[kc];
        float4 rv = xv[kc];
        float m[4] = {mv.x * inv, mv.y * inv, mv.z * inv, mv.w * inv};
        float r[4] = {rv.x, rv.y, rv.z, rv.w};
#pragma unroll
        for (int i = 0; i < 4; i++) {
            int k = kc * 4 + i;
            const float4* wl = reinterpret_cast<const float4*>(sWl + k * HID);
            const float4* wr = reinterpret_cast<const float4*>(sWr + k * HID);
#pragma unroll
            for (int j4 = 0; j4 < HID / 4; j4++) {
                float4 a = wl[j4];
                float4 b = wr[j4];
                acc[j4 * 4 + 0] += m[i] * a.x + r[i] * b.x;
                acc[j4 * 4 + 1] += m[i] * a.y + r[i] * b.y;
                acc[j4 * 4 + 2] += m[i] * a.z + r[i] * b.z;
                acc[j4 * 4 + 3] += m[i] * a.w + r[i] * b.w;
            }
        }
    }

    float4* outp = reinterpret_cast<float4*>(hout + (size_t)n * HID);
#pragma unroll
    for (int j4 = 0; j4 < HID / 4; j4++) {
        float4 o;
        o.x = acc[j4 * 4 + 0];
        o.y = acc[j4 * 4 + 1];
        o.z = acc[j4 * 4 + 2];
        o.w = acc[j4 * 4 + 3];
        if (RELU) {
            o.x = fmaxf(o.x, 0.0f); o.y = fmaxf(o.y, 0.0f);
            o.z = fmaxf(o.z, 0.0f); o.w = fmaxf(o.w, 0.0f);
        }
        outp[j4] = o;
    }
}

// ---------------- edge MLP: sigmoid(relu(relu([h_s,h_d,ea]@W1+b1)@W2+b2)@W3+b3) ----------------
// smem layout (floats):
//   sInT  [K1][128]   transposed inputs
//   sW1   [K1][64]
//   sZ1T  [64][128]
//   sW2   [64][32]
//   sZ2T  [32][128]
//   sW3[32], sB1[64], sB2[32], then sSrc[128], sDst[128] (ints)
#define EDGE_SMEM_FLOATS (K1*TILE_E + K1*64 + 64*TILE_E + 64*32 + 32*TILE_E + 32 + 64 + 32)
#define EDGE_SMEM_BYTES  (EDGE_SMEM_FLOATS*4 + 2*TILE_E*4)

__global__ __launch_bounds__(256)
void k_edge_mlp(const float* __restrict__ h,
                const int* __restrict__ src, const int* __restrict__ dst,
                const float* __restrict__ ea,
                const float* __restrict__ W1, const float* __restrict__ b1,
                const float* __restrict__ W2, const float* __restrict__ b2,
                const float* __restrict__ W3, const float* __restrict__ b3,
                float* __restrict__ out) {
    extern __shared__ float sm[];
    float* sInT = sm;                        // K1*128
    float* sW1  = sInT + K1 * TILE_E;        // K1*64
    float* sZ1T = sW1 + K1 * 64;             // 64*128
    float* sW2  = sZ1T + 64 * TILE_E;        // 64*32
    float* sZ2T = sW2 + 64 * 32;             // 32*128
    float* sW3  = sZ2T + 32 * TILE_E;        // 32
    float* sB1  = sW3 + 32;                  // 64
    float* sB2  = sB1 + 64;                  // 32
    int*   sSrc = reinterpret_cast<int*>(sB2 + 32);   // 128
    int*   sDst = sSrc + TILE_E;                      // 128

    const int tid = threadIdx.x;

    // stage weights once per block (persistent)
    for (int i = tid; i < K1 * 64; i += 256) sW1[i] = W1[i];
    for (int i = tid; i < 64 * 32; i += 256) sW2[i] = W2[i];
    if (tid < 32) sW3[tid] = W3[tid];
    if (tid < 64) sB1[tid] = b1[tid];
    if (tid < 32) sB2[tid] = b2[tid];
    const float bias3 = __ldg(&b3[0]);

    const int jt = tid & 7;      // output group
    const int et = tid >> 3;     // edge lane 0..31

    const int n_tiles = NE / TILE_E;   // 12500, exact
    for (int tile = blockIdx.x; tile < n_tiles; tile += gridDim.x) {
        const int e0 = tile * TILE_E;
        __syncthreads();
        if (tid < TILE_E) {
            sSrc[tid] = src[e0 + tid];
            sDst[tid] = dst[e0 + tid];
        }
        __syncthreads();

        // gather: sInT[k][e], conflict-free stores (lanes sweep e)
        for (int idx = tid; idx < 34 * TILE_E; idx += 256) {
            int c = idx >> 7;          // float4 chunk 0..33
            int e = idx & 127;
            float4 v;
            if (c < 16)       v = *reinterpret_cast<const float4*>(h + (size_t)sSrc[e] * HID + (size_t)c * 4);
            else if (c < 32)  v = *reinterpret_cast<const float4*>(h + (size_t)sDst[e] * HID + (size_t)(c - 16) * 4);
            else              v = *reinterpret_cast<const float4*>(ea + (size_t)(e0 + e) * 8 + (size_t)(c - 32) * 4);
            int k = c * 4;
            sInT[(k + 0) * TILE_E + e] = v.x;
            sInT[(k + 1) * TILE_E + e] = v.y;
            sInT[(k + 2) * TILE_E + e] = v.z;
            sInT[(k + 3) * TILE_E + e] = v.w;
        }
        __syncthreads();

        // stage 1: z1[128][64] = relu(In @ W1 + b1), micro-tile 4 edges x 8 outs
        {
            const int j0 = jt * 8;
            float acc[4][8];
#pragma unroll
            for (int i = 0; i < 4; i++)
#pragma unroll
                for (int jj = 0; jj < 8; jj++) acc[i][jj] = sB1[j0 + jj];

#pragma unroll 4
            for (int k = 0; k < K1; k++) {
                float a0 = sInT[k * TILE_E + et];
                float a1 = sInT[k * TILE_E + et + 32];
                float a2 = sInT[k * TILE_E + et + 64];
                float a3 = sInT[k * TILE_E + et + 96];
                float4 wA = *reinterpret_cast<const float4*>(sW1 + k * 64 + j0);
                float4 wB = *reinterpret_cast<const float4*>(sW1 + k * 64 + j0 + 4);
                float w[8] = {wA.x, wA.y, wA.z, wA.w, wB.x, wB.y, wB.z, wB.w};
#pragma unroll
                for (int jj = 0; jj < 8; jj++) {
                    acc[0][jj] += a0 * w[jj];
                    acc[1][jj] += a1 * w[jj];
                    acc[2][jj] += a2 * w[jj];
                    acc[3][jj] += a3 * w[jj];
                }
            }
#pragma unroll
            for (int jj = 0; jj < 8; jj++)
#pragma unroll
                for (int i = 0; i < 4; i++)
                    sZ1T[(j0 + jj) * TILE_E + et + 32 * i] = fmaxf(acc[i][jj], 0.0f);
        }
        __syncthreads();

        // stage 2: z2[128][32] = relu(z1 @ W2 + b2), micro-tile 4 edges x 4 outs
        {
            const int j0 = jt * 4;
            float acc[4][4];
#pragma unroll
            for (int i = 0; i < 4; i++)
#pragma unroll
                for (int jj = 0; jj < 4; jj++) acc[i][jj] = sB2[j0 + jj];

#pragma unroll 4
            for (int k = 0; k < 64; k++) {
                float a0 = sZ1T[k * TILE_E + et];
                float a1 = sZ1T[k * TILE_E + et + 32];
                float a2 = sZ1T[k * TILE_E + et + 64];
                float a3 = sZ1T[k * TILE_E + et + 96];
                float4 w4 = *reinterpret_cast<const float4*>(sW2 + k * 32 + j0);
                float w[4] = {w4.x, w4.y, w4.z, w4.w};
#pragma unroll
                for (int jj = 0; jj < 4; jj++) {
                    acc[0][jj] += a0 * w[jj];
                    acc[1][jj] += a1 * w[jj];
                    acc[2][jj] += a2 * w[jj];
                    acc[3][jj] += a3 * w[jj];
                }
            }
#pragma unroll
            for (int jj = 0; jj < 4; jj++)
#pragma unroll
                for (int i = 0; i < 4; i++)
                    sZ2T[(j0 + jj) * TILE_E + et + 32 * i] = fmaxf(acc[i][jj], 0.0f);
        }
        __syncthreads();

        // stage 3: out[e] = sigmoid(z2 . W3 + b3)
        if (tid < TILE_E) {
            float s = bias3;
#pragma unroll
            for (int k = 0; k < 32; k++) s += sZ2T[k * TILE_E + tid] * sW3[k];
            out[e0 + tid] = 1.0f / (1.0f + expf(-s));
        }
    }
}

// ---------------- launch ----------------
extern "C" void kernel_launch(void* const* d_in, const int* in_sizes, int n_in,
                              void* d_out, int out_size) {
    (void)in_sizes; (void)n_in; (void)out_size;
    const float* x   = (const float*)d_in[0];
    const int*   ei  = (const int*)d_in[1];
    const float* ea  = (const float*)d_in[2];
    const float* Wl0 = (const float*)d_in[3];
    const float* bl0 = (const float*)d_in[4];
    const float* Wr0 = (const float*)d_in[5];
    const float* Wl1 = (const float*)d_in[6];
    const float* bl1 = (const float*)d_in[7];
    const float* Wr1 = (const float*)d_in[8];
    const float* Wl2 = (const float*)d_in[9];
    const float* bl2 = (const float*)d_in[10];
    const float* Wr2 = (const float*)d_in[11];
    const float* W1  = (const float*)d_in[12];
    const float* b1  = (const float*)d_in[13];
    const float* W2  = (const float*)d_in[14];
    const float* b2  = (const float*)d_in[15];
    const float* W3  = (const float*)d_in[16];
    const float* b3  = (const float*)d_in[17];
    float* out = (float*)d_out;

    const int* src = ei;
    const int* dst = ei + NE;

    void *p_deg, *p_sum, *p_hA, *p_hB;
    cudaGetSymbolAddress(&p_deg, g_deg);
    cudaGetSymbolAddress(&p_sum, g_sum);
    cudaGetSymbolAddress(&p_hA, g_hA);
    cudaGetSymbolAddress(&p_hB, g_hB);
    float* hA = (float*)p_hA;
    float* hB = (float*)p_hB;

    cudaFuncSetAttribute(k_edge_mlp, cudaFuncAttributeMaxDynamicSharedMemorySize,
                         EDGE_SMEM_BYTES);

    // degree (shared by all 3 layers) + layer-0 sum
    cudaMemsetAsync(p_deg, 0, NN * sizeof(float), 0);
    cudaMemsetAsync(p_sum, 0, (size_t)NN * 32 * sizeof(float), 0);
    k_deg<<<(NE + 255) / 256, 256>>>(dst);

    // layer 0: IN=32
    k_scatter<32><<<(NE * 8 + 255) / 256, 256>>>(x, src, dst);
    k_node<32, true><<<(NN + 127) / 128, 128>>>(x, Wl0, bl0, Wr0, hA);

    // layer 1: IN=64
    cudaMemsetAsync(p_sum, 0, (size_t)NN * 64 * sizeof(float), 0);
    k_scatter<64><<<(NE * 16 + 255) / 256, 256>>>(hA, src, dst);
    k_node<64, true><<<(NN + 127) / 128, 128>>>(hA, Wl1, bl1, Wr1, hB);

    // layer 2: IN=64, no relu
    cudaMemsetAsync(p_sum, 0, (size_t)NN * 64 * sizeof(float), 0);
    k_scatter<64><<<(NE * 16 + 255) / 256, 256>>>(hB, src, dst);
    k_node<64, false><<<(NN + 127) / 128, 128>>>(hB, Wl2, bl2, Wr2, hA);

    // edge predictor
    k_edge_mlp<<<MLP_GRID, 256, EDGE_SMEM_BYTES>>>(hA, src, dst, ea,
                                                   W1, b1, W2, b2, W3, b3, out);
}